// round 2
// baseline (speedup 1.0000x reference)
#include <cuda_runtime.h>
#include <stdint.h>

#define VOCAB 100000
#define EMBED 128
#define NTOK  (4096 * 200)

// Scratch: transposed weight with bias fused: WT[v][e] = W[e][v] + b[e]
// 100000 * 128 * 4 B = 51.2 MB (fits in GB300's ~126 MB L2)
__device__ float g_WT[(size_t)VOCAB * EMBED];

// Flag: 1 if x is stored as int64, 0 if int32. Set by detect kernel each call.
__device__ int g_x_is64;

// ---------------------------------------------------------------------------
// Kernel 0: detect index dtype. Values are in [0, VOCAB). If the buffer is
// int64, every odd 32-bit word (high half) is 0. If int32, 1024 consecutive
// random indices being all zero is essentially impossible.
// Single block -> no inter-block race; deterministic per input.
// ---------------------------------------------------------------------------
__global__ void detect_dtype_kernel(const unsigned int* __restrict__ x32) {
    __shared__ int s_any;
    if (threadIdx.x == 0) s_any = 0;
    __syncthreads();
    // sample 1024 odd words
    unsigned int v = x32[2 * threadIdx.x + 1];
    if (v != 0) atomicOr(&s_any, 1);
    __syncthreads();
    if (threadIdx.x == 0) g_x_is64 = (s_any == 0) ? 1 : 0;
}

// ---------------------------------------------------------------------------
// Kernel 1: tiled transpose of W [EMBED, VOCAB] -> WT [VOCAB, EMBED], + bias.
// ---------------------------------------------------------------------------
__global__ void transpose_bias_kernel(const float* __restrict__ W,
                                      const float* __restrict__ b) {
    __shared__ float tile[32][33];

    const int v0 = blockIdx.x * 32;
    const int e0 = blockIdx.y * 32;
    const int tx = threadIdx.x;
    const int ty = threadIdx.y;

    tile[ty][tx] = W[(size_t)(e0 + ty) * VOCAB + (v0 + tx)];
    __syncthreads();

    g_WT[(size_t)(v0 + ty) * EMBED + (e0 + tx)] = tile[tx][ty] + __ldg(&b[e0 + tx]);
}

// ---------------------------------------------------------------------------
// Kernel 2: gather. One warp per token; lane moves one float4 (512 B/token).
// ---------------------------------------------------------------------------
__global__ void gather_kernel(const unsigned int* __restrict__ x32,
                              float4* __restrict__ out) {
    const int warp_id = (blockIdx.x * blockDim.x + threadIdx.x) >> 5;
    const int lane    = threadIdx.x & 31;
    if (warp_id >= NTOK) return;

    long long v;
    if (g_x_is64) {
        // little-endian int64: low word is the value (values < 2^31)
        v = (long long)x32[2 * warp_id];
    } else {
        v = (long long)(int)x32[warp_id];
    }
    // clamp: wrong data should fail rel_err, never crash
    if (v < 0) v = 0;
    if (v >= VOCAB) v = VOCAB - 1;

    const float4* row = reinterpret_cast<const float4*>(g_WT + (size_t)v * EMBED);
    out[(size_t)warp_id * 32 + lane] = __ldg(&row[lane]);
}

extern "C" void kernel_launch(void* const* d_in, const int* in_sizes, int n_in,
                              void* d_out, int out_size) {
    // Identify inputs by element count (robust to metadata ordering):
    //   x: 819200, W: 12800000, b: 128
    const void*  x = nullptr;
    const float* W = nullptr;
    const float* b = nullptr;
    for (int i = 0; i < n_in; i++) {
        if (in_sizes[i] == NTOK)                 x = d_in[i];
        else if (in_sizes[i] == VOCAB * EMBED)   W = (const float*)d_in[i];
        else if (in_sizes[i] == EMBED)           b = (const float*)d_in[i];
    }
    float4* out = (float4*)d_out;

    // 0) detect int64 vs int32 index storage
    detect_dtype_kernel<<<1, 1024>>>((const unsigned int*)x);

    // 1) W -> WT (+bias)
    {
        dim3 block(32, 32);
        dim3 grid(VOCAB / 32, EMBED / 32);  // 3125 x 4
        transpose_bias_kernel<<<grid, block>>>(W, b);
    }

    // 2) gather rows of WT at x
    {
        const int threads = 256;
        const int warps_per_block = threads / 32;
        const int blocks = (NTOK + warps_per_block - 1) / warps_per_block;
        gather_kernel<<<blocks, threads>>>((const unsigned int*)x, out);
    }
}

// round 6
// speedup vs baseline: 1.1688x; 1.1688x over previous
#include <cuda_runtime.h>
#include <stdint.h>

#define VOCAB 100000
#define EMBED 128
#define NTOK  (4096 * 200)

// Scratch: transposed weight with bias fused: WT[v][e] = W[e][v] + b[e]
// 100000 * 128 * 4 B = 51.2 MB (fits in GB300's ~126 MB L2 if not thrashed)
__device__ float g_WT[(size_t)VOCAB * EMBED];

// Flag: 1 if x is stored as int64, 0 if int32.
__device__ int g_x_is64;

// ---------------------------------------------------------------------------
// Kernel 0: detect index dtype. Values are in [0, VOCAB). If the buffer is
// int64, every odd 32-bit word (high half) is 0. 64 random samples all-zero
// under int32 has probability ~0 -> effectively impossible.
// ---------------------------------------------------------------------------
__global__ void detect_dtype_kernel(const unsigned int* __restrict__ x32) {
    unsigned int v = x32[2 * threadIdx.x + 1];           // odd words, 64 samples
    unsigned int any = __ballot_sync(0xFFFFFFFFu, v != 0) |
                       __ballot_sync(0xFFFFFFFFu, x32[2 * (threadIdx.x + 32) + 1] != 0);
    if (threadIdx.x == 0) g_x_is64 = (any == 0) ? 1 : 0;
}

// ---------------------------------------------------------------------------
// Kernel 1: tiled transpose of W [EMBED, VOCAB] -> WT [VOCAB, EMBED], + bias.
// float4-vectorized along vocab: each block handles a 32(e) x 128(v) slab.
// block = (32,32): thread (tx,ty) loads W[e0+ty][v0 + 4*tx .. +3] as float4.
// ---------------------------------------------------------------------------
__global__ void transpose_bias_kernel(const float* __restrict__ W,
                                      const float* __restrict__ b) {
    __shared__ float tile[32][129];   // [e][v_local], pad to kill conflicts

    const int v0 = blockIdx.x * 128;  // VOCAB/128 = 781.25 -> 782 blocks, guard
    const int e0 = blockIdx.y * 32;
    const int tx = threadIdx.x;       // 0..31 (vocab quads)
    const int ty = threadIdx.y;       // 0..31 (embed rows)

    const int v_quad = v0 + 4 * tx;
    if (v_quad + 3 < VOCAB) {
        const float4 w4 = *reinterpret_cast<const float4*>(
            &W[(size_t)(e0 + ty) * VOCAB + v_quad]);
        tile[ty][4 * tx + 0] = w4.x;
        tile[ty][4 * tx + 1] = w4.y;
        tile[ty][4 * tx + 2] = w4.z;
        tile[ty][4 * tx + 3] = w4.w;
    } else {
        for (int k = 0; k < 4; k++) {
            int v = v_quad + k;
            if (v < VOCAB)
                tile[ty][4 * tx + k] = W[(size_t)(e0 + ty) * VOCAB + v];
        }
    }
    __syncthreads();

    // Write WT rows: 128 v-rows in this slab, each row segment is 32 floats
    // at embed offset e0. Thread layout: ty picks 4 v-rows, tx picks embed.
    const float bias = __ldg(&b[e0 + tx]);
    #pragma unroll
    for (int r = 0; r < 4; r++) {
        const int v_local = ty * 4 + r;
        const int v = v0 + v_local;
        if (v < VOCAB)
            g_WT[(size_t)v * EMBED + (e0 + tx)] = tile[tx][v_local] + bias;
    }
}

// ---------------------------------------------------------------------------
// Kernel 2: gather. One warp per token; lane moves one float4 (512 B/token).
// WT reads cached (L2 reuse ~8x); output stores streamed (__stcs) so the
// 419 MB write stream does not evict WT from L2.
// ---------------------------------------------------------------------------
__global__ void gather_kernel(const unsigned int* __restrict__ x32,
                              float4* __restrict__ out) {
    const int warp_id = (blockIdx.x * blockDim.x + threadIdx.x) >> 5;
    const int lane    = threadIdx.x & 31;
    if (warp_id >= NTOK) return;

    long long v;
    if (g_x_is64) {
        v = (long long)x32[2 * warp_id];       // little-endian low word
    } else {
        v = (long long)(int)x32[warp_id];
    }
    if (v < 0) v = 0;
    if (v >= VOCAB) v = VOCAB - 1;

    const float4* row = reinterpret_cast<const float4*>(g_WT + (size_t)v * EMBED);
    const float4 val = __ldg(&row[lane]);
    __stcs(&out[(size_t)warp_id * 32 + lane], val);   // streaming store
}

extern "C" void kernel_launch(void* const* d_in, const int* in_sizes, int n_in,
                              void* d_out, int out_size) {
    // Identify inputs by element count (robust to metadata ordering):
    //   x: 819200, W: 12800000, b: 128
    const void*  x = nullptr;
    const float* W = nullptr;
    const float* b = nullptr;
    for (int i = 0; i < n_in; i++) {
        if (in_sizes[i] == NTOK)                 x = d_in[i];
        else if (in_sizes[i] == VOCAB * EMBED)   W = (const float*)d_in[i];
        else if (in_sizes[i] == EMBED)           b = (const float*)d_in[i];
    }
    float4* out = (float4*)d_out;

    // 0) detect int64 vs int32 index storage (1 warp)
    detect_dtype_kernel<<<1, 32>>>((const unsigned int*)x);

    // 1) W -> WT (+bias), vectorized
    {
        dim3 block(32, 32);
        dim3 grid((VOCAB + 127) / 128, EMBED / 32);  // 782 x 4
        transpose_bias_kernel<<<grid, block>>>(W, b);
    }

    // 2) gather rows of WT at x
    {
        const int threads = 256;
        const int warps_per_block = threads / 32;
        const int blocks = (NTOK + warps_per_block - 1) / warps_per_block;
        gather_kernel<<<blocks, threads>>>((const unsigned int*)x, out);
    }
}

// round 10
// speedup vs baseline: 1.6172x; 1.3837x over previous
#include <cuda_runtime.h>
#include <stdint.h>

#define VOCAB 100000
#define EMBED 128
#define NTOK  (4096 * 200)

// Scratch: transposed weight with bias fused: WT[v][e] = W[e][v] + b[e]
// 100000 * 128 * 4 B = 51.2 MB (fits in GB300's ~126 MB L2 if not thrashed)
__device__ float g_WT[(size_t)VOCAB * EMBED];

// Flag: 1 if x is stored as int64, 0 if int32. Set inside transpose kernel.
__device__ int g_x_is64;

// ---------------------------------------------------------------------------
// Kernel 1: tiled transpose of W [EMBED, VOCAB] -> WT [VOCAB, EMBED], + bias.
// float4-vectorized along vocab; W read with __ldcs (read-once, evict-first)
// so the W stream doesn't evict freshly written WT lines from L2.
// Also folds the index-dtype detection (block (0,0), warp ty==0): if x is
// int64, every odd 32-bit word (high half of values < 100000) is 0; 64
// all-zero samples under int32 is essentially impossible.
// ---------------------------------------------------------------------------
__global__ void transpose_bias_kernel(const float* __restrict__ W,
                                      const float* __restrict__ b,
                                      const unsigned int* __restrict__ x32) {
    __shared__ float tile[32][129];   // [e][v_local], pad to kill conflicts

    const int tx = threadIdx.x;       // 0..31 (vocab quads)
    const int ty = threadIdx.y;       // 0..31 (embed rows)

    // --- folded dtype detection (one warp of one block) ---
    if (blockIdx.x == 0 && blockIdx.y == 0 && ty == 0) {
        unsigned int any =
            __ballot_sync(0xFFFFFFFFu, x32[2 * tx + 1] != 0) |
            __ballot_sync(0xFFFFFFFFu, x32[2 * (tx + 32) + 1] != 0);
        if (tx == 0) g_x_is64 = (any == 0) ? 1 : 0;
    }

    const int v0 = blockIdx.x * 128;  // 782 blocks along vocab, guard tail
    const int e0 = blockIdx.y * 32;

    const int v_quad = v0 + 4 * tx;
    if (v_quad + 3 < VOCAB) {
        const float4 w4 = __ldcs(reinterpret_cast<const float4*>(
            &W[(size_t)(e0 + ty) * VOCAB + v_quad]));
        tile[ty][4 * tx + 0] = w4.x;
        tile[ty][4 * tx + 1] = w4.y;
        tile[ty][4 * tx + 2] = w4.z;
        tile[ty][4 * tx + 3] = w4.w;
    } else {
        for (int k = 0; k < 4; k++) {
            int v = v_quad + k;
            if (v < VOCAB)
                tile[ty][4 * tx + k] = __ldcs(&W[(size_t)(e0 + ty) * VOCAB + v]);
        }
    }
    __syncthreads();

    // Write WT rows (default caching: we WANT these resident in L2).
    const float bias = __ldg(&b[e0 + tx]);
    #pragma unroll
    for (int r = 0; r < 4; r++) {
        const int v_local = ty * 4 + r;
        const int v = v0 + v_local;
        if (v < VOCAB)
            g_WT[(size_t)v * EMBED + (e0 + tx)] = tile[tx][v_local] + bias;
    }
}

// ---------------------------------------------------------------------------
// Kernel 2: gather. TWO tokens per warp; each lane carries two independent
// float4 load->store chains (MLP=2) for better latency hiding. Reads cached
// (L2-resident WT), output stores streamed (__stcs) so the 419 MB write
// stream does not evict WT from L2.
// ---------------------------------------------------------------------------
__global__ void gather_kernel(const unsigned int* __restrict__ x32,
                              float4* __restrict__ out) {
    const int warp = (blockIdx.x * blockDim.x + threadIdx.x) >> 5;
    const int lane = threadIdx.x & 31;
    const int t0 = 2 * warp;
    const int t1 = t0 + 1;          // NTOK is even: t1 valid whenever t0 is
    if (t0 >= NTOK) return;

    const int is64 = g_x_is64;
    long long v0, v1;
    if (is64) {
        v0 = (long long)x32[2 * t0];     // little-endian low word
        v1 = (long long)x32[2 * t1];
    } else {
        v0 = (long long)(int)x32[t0];
        v1 = (long long)(int)x32[t1];
    }
    // clamp: wrong data should fail rel_err, never crash
    if (v0 < 0) v0 = 0; if (v0 >= VOCAB) v0 = VOCAB - 1;
    if (v1 < 0) v1 = 0; if (v1 >= VOCAB) v1 = VOCAB - 1;

    const float4* row0 = reinterpret_cast<const float4*>(g_WT + (size_t)v0 * EMBED);
    const float4* row1 = reinterpret_cast<const float4*>(g_WT + (size_t)v1 * EMBED);

    // two independent load chains -> overlapped memory latency
    const float4 a = __ldg(&row0[lane]);
    const float4 c = __ldg(&row1[lane]);
    __stcs(&out[(size_t)t0 * 32 + lane], a);
    __stcs(&out[(size_t)t1 * 32 + lane], c);
}

extern "C" void kernel_launch(void* const* d_in, const int* in_sizes, int n_in,
                              void* d_out, int out_size) {
    // Identify inputs by element count (robust to metadata ordering):
    //   x: 819200, W: 12800000, b: 128
    const void*  x = nullptr;
    const float* W = nullptr;
    const float* b = nullptr;
    for (int i = 0; i < n_in; i++) {
        if (in_sizes[i] == NTOK)                 x = d_in[i];
        else if (in_sizes[i] == VOCAB * EMBED)   W = (const float*)d_in[i];
        else if (in_sizes[i] == EMBED)           b = (const float*)d_in[i];
    }
    float4* out = (float4*)d_out;

    // 1) W -> WT (+bias), vectorized; dtype detection folded in
    {
        dim3 block(32, 32);
        dim3 grid((VOCAB + 127) / 128, EMBED / 32);  // 782 x 4
        transpose_bias_kernel<<<grid, block>>>(W, b, (const unsigned int*)x);
    }

    // 2) gather rows of WT at x (2 tokens per warp)
    {
        const int threads = 256;                        // 8 warps
        const int warps_needed = NTOK / 2;              // 409600
        const int blocks = (warps_needed + 7) / 8;      // 51200
        gather_kernel<<<blocks, threads>>>((const unsigned int*)x, out);
    }
}